// round 4
// baseline (speedup 1.0000x reference)
#include <cuda_runtime.h>
#include <cuda_bf16.h>
#include <cstdint>

// YOLO layer: (B, 3*85, 76, 76) fp32 -> (B, 3*76*76, 85) fp32
// HBM-bound transpose + elementwise epilogue.
//
// Per CTA: one (b, anchor, grid-row t): 85 channels x 76 cols.
// Warp-task mapping chosen for CONFLICT-FREE smem scatter:
//   each warp-task = 4 channels x 8 vec4:  k4 = lane>>3, q8 = lane&7
//   STS address word = 340*q + k  ->  bank = (20*q8 + k4 + c) % 32 : all 32
//   lanes distinct. LDG: 8 lanes read 128B contiguous per channel.
// Store: one cp.async.bulk shared->global of the 25840B tile (already in
// output order, contiguous destination).

#define G     76
#define C     85
#define NA    3
#define TPB   256
#define NW    (TPB / 32)       // 8 warps
#define TILE  (C * G)          // 6460 floats
#define VPC   (G / 4)          // 19 vec4 per channel row
#define KT    ((C + 3) / 4)    // 22 channel-tiles of 4
#define QT    ((VPC + 7) / 8)  // 3 q-tiles of 8
#define NTASK (KT * QT)        // 66 warp-tasks

__device__ __forceinline__ float sigf(float v) {
    return __fdividef(1.0f, 1.0f + __expf(-v));
}

__global__ __launch_bounds__(TPB)
void yolo_kernel(const float* __restrict__ in,
                 const void*  __restrict__ imgdim_p,
                 float* __restrict__ out)
{
    __shared__ __align__(16) float tile[TILE];

    const int blk = blockIdx.x;
    const int t   = blk % G;              // grid row (grid_y)
    const int a   = (blk / G) % NA;       // anchor
    const int b   = blk / (G * NA);       // batch

    float stride = 8.0f;
    if (imgdim_p) {
        int iv = *(const int*)imgdim_p;
        float dim = (iv > 0 && iv < (1 << 20)) ? (float)iv : __int_as_float(iv);
        stride = dim / (float)G;
    }

    const float AW[NA] = {116.0f, 156.0f, 373.0f};
    const float AH[NA] = { 90.0f, 198.0f, 326.0f};
    const float aw = AW[a], ah = AH[a];
    const float gy = (float)t;

    const float* base = in + ((size_t)(b * NA + a) * C) * (G * G) + (size_t)t * G;

    const int warp = threadIdx.x >> 5;
    const int lane = threadIdx.x & 31;
    const int k4   = lane >> 3;           // 0..3  channel within tile
    const int q8   = lane & 7;            // 0..7  vec4 within tile

    for (int task = warp; task < NTASK; task += NW) {
        const int qt = task / KT;         // 0..2
        const int kt = task - qt * KT;    // 0..21
        const int k  = kt * 4 + k4;       // channel
        const int q  = qt * 8 + q8;       // vec4 index in row
        if (k < C && q < VPC) {
            const float4 v = __ldcs((const float4*)(base + (size_t)k * (G * G)) + q);
            const int s0 = q * 4;

            float r0, r1, r2, r3;
            if (k >= 4) {
                r0 = sigf(v.x); r1 = sigf(v.y); r2 = sigf(v.z); r3 = sigf(v.w);
            } else if (k == 0) {
                r0 = (sigf(v.x) + (float)(s0 + 0)) * stride;
                r1 = (sigf(v.y) + (float)(s0 + 1)) * stride;
                r2 = (sigf(v.z) + (float)(s0 + 2)) * stride;
                r3 = (sigf(v.w) + (float)(s0 + 3)) * stride;
            } else if (k == 1) {
                r0 = (sigf(v.x) + gy) * stride;
                r1 = (sigf(v.y) + gy) * stride;
                r2 = (sigf(v.z) + gy) * stride;
                r3 = (sigf(v.w) + gy) * stride;
            } else if (k == 2) {
                r0 = __expf(v.x) * aw; r1 = __expf(v.y) * aw;
                r2 = __expf(v.z) * aw; r3 = __expf(v.w) * aw;
            } else {
                r0 = __expf(v.x) * ah; r1 = __expf(v.y) * ah;
                r2 = __expf(v.z) * ah; r3 = __expf(v.w) * ah;
            }
            float* p = &tile[(unsigned)s0 * C + k];  // conflict-free banks
            p[0]     = r0;
            p[C]     = r1;
            p[2 * C] = r2;
            p[3 * C] = r3;
        }
    }
    __syncthreads();

    // Single bulk async store: tile[] == the contiguous 76x85 output block.
    if (threadIdx.x == 0) {
        float* obase = out + ((size_t)(b * NA + a) * (G * G) + (size_t)t * G) * C;
        uint32_t saddr;
        asm("{ .reg .u64 t0; cvta.to.shared.u64 t0, %1; cvt.u32.u64 %0, t0; }"
            : "=r"(saddr) : "l"(tile));
        asm volatile("fence.proxy.async.shared::cta;" ::: "memory");
        asm volatile("cp.async.bulk.global.shared::cta.bulk_group [%0], [%1], %2;"
                     :: "l"(obase), "r"(saddr), "n"(TILE * 4) : "memory");
        asm volatile("cp.async.bulk.commit_group;" ::: "memory");
        asm volatile("cp.async.bulk.wait_group 0;" ::: "memory");
    }
}

extern "C" void kernel_launch(void* const* d_in, const int* in_sizes, int n_in,
                              void* d_out, int out_size)
{
    const float* x = (const float*)d_in[0];
    const void*  dim = (n_in > 1) ? d_in[1] : nullptr;
    const int B = in_sizes[0] / (NA * C * G * G);   // 64 for the bench shape

    dim3 grid(B * NA * G);
    yolo_kernel<<<grid, TPB>>>(x, dim, (float*)d_out);
}

// round 5
// speedup vs baseline: 1.8262x; 1.8262x over previous
#include <cuda_runtime.h>
#include <cuda_bf16.h>
#include <cstdint>

// YOLO layer: (B, 3*85, 76, 76) fp32 -> (B, 3*76*76, 85) fp32
// HBM-bound transpose + elementwise epilogue. Round-2 structure (best) with
// a two-phase batched load loop to raise memory-level parallelism:
//   phase 1: each thread issues its 4 (predicated) vec4 LDGs back-to-back
//   phase 2: transform + smem scatter (output order, stride 85)
//   store  : single cp.async.bulk shared->global of the contiguous 25840B tile
// TPB=512, 26KB smem -> 4 CTAs/SM = 2048 thr/SM (full occupancy).

#define G     76
#define C     85
#define NA    3
#define TPB   512
#define TILE  (C * G)         // 6460 floats (25840 B)
#define TILE4 (TILE / 4)      // 1615 vec4
#define VPC   (G / 4)         // 19 vec4 per channel row
#define NIT   4               // 512*4 = 2048 >= 1615

__device__ __forceinline__ float sigf(float v) {
    return __fdividef(1.0f, 1.0f + __expf(-v));
}

__global__ __launch_bounds__(TPB)
void yolo_kernel(const float* __restrict__ in,
                 const void*  __restrict__ imgdim_p,
                 float* __restrict__ out)
{
    __shared__ __align__(16) float tile[TILE];

    const int blk = blockIdx.x;
    const int t   = blk % G;              // grid row (grid_y)
    const int a   = (blk / G) % NA;       // anchor
    const int b   = blk / (G * NA);       // batch

    float stride = 8.0f;
    if (imgdim_p) {
        int iv = *(const int*)imgdim_p;
        float dim = (iv > 0 && iv < (1 << 20)) ? (float)iv : __int_as_float(iv);
        stride = dim / (float)G;
    }

    const float AW[NA] = {116.0f, 156.0f, 373.0f};
    const float AH[NA] = { 90.0f, 198.0f, 326.0f};
    const float aw = AW[a], ah = AH[a];
    const float gy = (float)t;

    const float* base = in + ((size_t)(b * NA + a) * C) * (G * G) + (size_t)t * G;

    // ---- phase 1: batch all loads (4 independent LDG.128 in flight) ----
    float4 v[NIT];
    #pragma unroll
    for (int j = 0; j < NIT; j++) {
        const unsigned i = threadIdx.x + j * TPB;
        if (i < TILE4) {
            const unsigned k = i / VPC;
            const unsigned q = i - k * VPC;
            v[j] = __ldcs((const float4*)(base + (size_t)k * (G * G)) + q);
        }
    }

    // ---- phase 2: transform + scatter to smem in output order ----
    #pragma unroll
    for (int j = 0; j < NIT; j++) {
        const unsigned i = threadIdx.x + j * TPB;
        if (i < TILE4) {
            const unsigned k = i / VPC;        // channel 0..84
            const unsigned q = i - k * VPC;    // vec4 index 0..18
            const int s0 = q * 4;
            const float4 w = v[j];

            float r0, r1, r2, r3;
            if (k >= 4) {
                r0 = sigf(w.x); r1 = sigf(w.y); r2 = sigf(w.z); r3 = sigf(w.w);
            } else if (k == 0) {
                r0 = (sigf(w.x) + (float)(s0 + 0)) * stride;
                r1 = (sigf(w.y) + (float)(s0 + 1)) * stride;
                r2 = (sigf(w.z) + (float)(s0 + 2)) * stride;
                r3 = (sigf(w.w) + (float)(s0 + 3)) * stride;
            } else if (k == 1) {
                r0 = (sigf(w.x) + gy) * stride;
                r1 = (sigf(w.y) + gy) * stride;
                r2 = (sigf(w.z) + gy) * stride;
                r3 = (sigf(w.w) + gy) * stride;
            } else if (k == 2) {
                r0 = __expf(w.x) * aw; r1 = __expf(w.y) * aw;
                r2 = __expf(w.z) * aw; r3 = __expf(w.w) * aw;
            } else {
                r0 = __expf(w.x) * ah; r1 = __expf(w.y) * ah;
                r2 = __expf(w.z) * ah; r3 = __expf(w.w) * ah;
            }
            float* p = &tile[(unsigned)s0 * C + k];
            p[0]     = r0;
            p[C]     = r1;
            p[2 * C] = r2;
            p[3 * C] = r3;
        }
    }
    __syncthreads();

    // ---- single bulk async store of the contiguous 76x85 output block ----
    if (threadIdx.x == 0) {
        float* obase = out + ((size_t)(b * NA + a) * (G * G) + (size_t)t * G) * C;
        uint32_t saddr;
        asm("{ .reg .u64 t0; cvta.to.shared.u64 t0, %1; cvt.u32.u64 %0, t0; }"
            : "=r"(saddr) : "l"(tile));
        asm volatile("fence.proxy.async.shared::cta;" ::: "memory");
        asm volatile("cp.async.bulk.global.shared::cta.bulk_group [%0], [%1], %2;"
                     :: "l"(obase), "r"(saddr), "n"(TILE * 4) : "memory");
        asm volatile("cp.async.bulk.commit_group;" ::: "memory");
        asm volatile("cp.async.bulk.wait_group 0;" ::: "memory");
    }
}

extern "C" void kernel_launch(void* const* d_in, const int* in_sizes, int n_in,
                              void* d_out, int out_size)
{
    const float* x = (const float*)d_in[0];
    const void*  dim = (n_in > 1) ? d_in[1] : nullptr;
    const int B = in_sizes[0] / (NA * C * G * G);   // 64 for the bench shape

    dim3 grid(B * NA * G);
    yolo_kernel<<<grid, TPB>>>(x, dim, (float*)d_out);
}